// round 9
// baseline (speedup 1.0000x reference)
#include <cuda_runtime.h>
#include <cuda_bf16.h>
#include <math.h>

// Problem constants
#define B_   4
#define N_   512
#define FIN  64
#define FOUT 128
#define NCH  8           // i-chunks (64 i per chunk) — matches K2 grid.y

// Scratch (allocation-free rule: __device__ globals)
static __device__ float g_pi   [B_ * N_ * FOUT];          // nodes @ edge_W[:,F:].T
static __device__ float g_pjb  [B_ * N_ * FOUT];          // nodes @ edge_W[:,:F].T + edge_b
static __device__ float g_h    [B_ * N_ * FOUT];          // full MLP output
static __device__ float g_part [B_ * NCH * N_ * FOUT];    // partial sum_i edges (8MB)

__device__ __forceinline__ float celu1(float x) {
    return x > 0.f ? x : expm1f(x);
}

// ---------------------------------------------------------------------------
// K1: 8 node rows per block, 256 threads = (f 0..127) x (row-half g 0..1).
// Each thread keeps only 4 accumulators; weights staged in a 32KB SMEM buffer
// per layer (64KB matrices staged as two k-chunks). All FMA operands from
// SMEM: activations are warp-broadcast LDS, weights conflict-free LDS.128.
// grid = B*N/8 = 256 blocks.
// ---------------------------------------------------------------------------
__global__ __launch_bounds__(256) void k1_pernode(
    const float* __restrict__ nodes,
    const float* __restrict__ eW, const float* __restrict__ eb,
    const float* __restrict__ W0, const float* __restrict__ b0,
    const float* __restrict__ W1, const float* __restrict__ b1,
    const float* __restrict__ W2, const float* __restrict__ b2)
{
    const int row0  = blockIdx.x * 8;
    const int tid   = threadIdx.x;
    const int f     = tid & 127;
    const int rbase = (tid >> 7) * 4;     // rows rbase..rbase+3 of the 8

    __shared__ float xs [8 * FIN];        // 2KB
    __shared__ float h0s[8 * FOUT];       // 4KB
    __shared__ float h1s[8 * FOUT];       // 4KB
    __shared__ float wb [8192];           // 32KB weight stage

    float4* x4  = (float4*)xs;
    float4* h04 = (float4*)h0s;
    float4* h14 = (float4*)h1s;
    float4* wb4 = (float4*)wb;

    // load x (8 rows x 64 f = 128 float4) + stage eW pj-half (cols 0..63)
    if (tid < 128) {
        const float4* gx = (const float4*)(nodes + (size_t)row0 * FIN);
        x4[tid] = gx[tid];
    }
    {
        const float4* Ws = (const float4*)eW;   // rows of 32 float4
        #pragma unroll
        for (int t = tid; t < 2048; t += 256)
            wb4[t] = Ws[(t >> 4) * 32 + (t & 15)];
    }
    __syncthreads();

    float acc[4];

    // --- edge pj: g_pjb = x @ eW[:, :64].T + eb ---
    #pragma unroll
    for (int r = 0; r < 4; r++) acc[r] = 0.f;
    #pragma unroll
    for (int k = 0; k < 16; k++) {
        float4 w = wb4[f * 16 + k];
        #pragma unroll
        for (int r = 0; r < 4; r++) {
            float4 v = x4[(rbase + r) * 16 + k];
            acc[r] += w.x*v.x + w.y*v.y + w.z*v.z + w.w*v.w;
        }
    }
    {
        const float ebf = eb[f];
        #pragma unroll
        for (int r = 0; r < 4; r++)
            g_pjb[(size_t)(row0 + rbase + r) * FOUT + f] = acc[r] + ebf;
    }
    __syncthreads();

    // --- stage eW pi-half (cols 64..127), compute g_pi ---
    {
        const float4* Ws = (const float4*)eW;
        #pragma unroll
        for (int t = tid; t < 2048; t += 256)
            wb4[t] = Ws[(t >> 4) * 32 + 16 + (t & 15)];
    }
    __syncthreads();

    #pragma unroll
    for (int r = 0; r < 4; r++) acc[r] = 0.f;
    #pragma unroll
    for (int k = 0; k < 16; k++) {
        float4 w = wb4[f * 16 + k];
        #pragma unroll
        for (int r = 0; r < 4; r++) {
            float4 v = x4[(rbase + r) * 16 + k];
            acc[r] += w.x*v.x + w.y*v.y + w.z*v.z + w.w*v.w;
        }
    }
    #pragma unroll
    for (int r = 0; r < 4; r++)
        g_pi[(size_t)(row0 + rbase + r) * FOUT + f] = acc[r];
    __syncthreads();

    // --- stage W0 (128x64 = 2048 float4), layer0 + CELU ---
    {
        const float4* Ws = (const float4*)W0;
        #pragma unroll
        for (int t = tid; t < 2048; t += 256)
            wb4[t] = Ws[t];
    }
    __syncthreads();
    {
        const float bf = b0[f];
        #pragma unroll
        for (int r = 0; r < 4; r++) acc[r] = bf;
        #pragma unroll
        for (int k = 0; k < 16; k++) {
            float4 w = wb4[f * 16 + k];
            #pragma unroll
            for (int r = 0; r < 4; r++) {
                float4 v = x4[(rbase + r) * 16 + k];
                acc[r] += w.x*v.x + w.y*v.y + w.z*v.z + w.w*v.w;
            }
        }
        #pragma unroll
        for (int r = 0; r < 4; r++)
            h0s[(rbase + r) * FOUT + f] = celu1(acc[r]);
    }
    __syncthreads();

    // --- layer1 (128x128) in two 32KB k-chunks + CELU ---
    {
        const float bf = b1[f];
        #pragma unroll
        for (int r = 0; r < 4; r++) acc[r] = bf;
        #pragma unroll
        for (int hc = 0; hc < 2; hc++) {
            const float4* Ws = (const float4*)W1;
            #pragma unroll
            for (int t = tid; t < 2048; t += 256)
                wb4[t] = Ws[(t >> 4) * 32 + hc * 16 + (t & 15)];
            __syncthreads();
            #pragma unroll
            for (int k = 0; k < 16; k++) {
                float4 w = wb4[f * 16 + k];
                #pragma unroll
                for (int r = 0; r < 4; r++) {
                    float4 v = h04[(rbase + r) * 32 + hc * 16 + k];
                    acc[r] += w.x*v.x + w.y*v.y + w.z*v.z + w.w*v.w;
                }
            }
            __syncthreads();
        }
        #pragma unroll
        for (int r = 0; r < 4; r++)
            h1s[(rbase + r) * FOUT + f] = celu1(acc[r]);
    }
    __syncthreads();

    // --- layer2 (128x128) in two 32KB k-chunks -> g_h ---
    {
        const float bf = b2[f];
        #pragma unroll
        for (int r = 0; r < 4; r++) acc[r] = bf;
        #pragma unroll
        for (int hc = 0; hc < 2; hc++) {
            const float4* Ws = (const float4*)W2;
            #pragma unroll
            for (int t = tid; t < 2048; t += 256)
                wb4[t] = Ws[(t >> 4) * 32 + hc * 16 + (t & 15)];
            __syncthreads();
            #pragma unroll
            for (int k = 0; k < 16; k++) {
                float4 w = wb4[f * 16 + k];
                #pragma unroll
                for (int r = 0; r < 4; r++) {
                    float4 v = h14[(rbase + r) * 32 + hc * 16 + k];
                    acc[r] += w.x*v.x + w.y*v.y + w.z*v.z + w.w*v.w;
                }
            }
            __syncthreads();
        }
        #pragma unroll
        for (int r = 0; r < 4; r++)
            g_h[(size_t)(row0 + rbase + r) * FOUT + f] = acc[r];
    }
}

// ---------------------------------------------------------------------------
// K2: edges writer WITH fused i-partial reduction. (unchanged from R8)
// Tile: 64 (i) x 16 (j) per block. grid = (N/16, N/64, B) = 32x8x4, 256 thr.
// ---------------------------------------------------------------------------
__global__ __launch_bounds__(256) void k2_edges(
    const float* __restrict__ sk, float* __restrict__ edges)
{
    const int b  = blockIdx.z;
    const int iy = blockIdx.y;           // i-chunk 0..7
    const int i0 = iy * 64;
    const int j0 = blockIdx.x * 16;
    const int tid = threadIdx.x;

    __shared__ float4 spi [64][32];      // 32KB
    __shared__ float4 spjb[16][32];      // 8KB
    __shared__ float  ssk [64][16];      // 4KB

    const float4* gpi  = (const float4*)(g_pi  + ((size_t)(b * N_ + i0)) * FOUT);
    const float4* gpjb = (const float4*)(g_pjb + ((size_t)(b * N_ + j0)) * FOUT);
    #pragma unroll
    for (int t = tid; t < 2048; t += 256)
        spi[t >> 5][t & 31] = gpi[t];
    #pragma unroll
    for (int t = tid; t < 512; t += 256)
        spjb[t >> 5][t & 31] = gpjb[t];
    #pragma unroll
    for (int t = tid; t < 1024; t += 256) {
        int ii = t >> 4, jj = t & 15;
        ssk[ii][jj] = sk[((size_t)(b * N_ + i0 + ii)) * N_ + j0 + jj];
    }
    __syncthreads();

    const int lane = tid & 31;
    const int w    = tid >> 5;           // warp 0..7 -> jj in {w, w+8}

    const float4 c0 = spjb[w][lane];
    const float4 c1 = spjb[w + 8][lane];

    float4 acc0 = make_float4(0.f, 0.f, 0.f, 0.f);
    float4 acc1 = make_float4(0.f, 0.f, 0.f, 0.f);

    float4* __restrict__ e4 = (float4*)edges;
    const size_t base = ((size_t)(b * N_ + i0) * N_ + j0) * 32 + lane;

    #pragma unroll 4
    for (int ii = 0; ii < 64; ii++) {
        float4 a  = spi[ii][lane];
        float  s0 = ssk[ii][w];
        float  s1 = ssk[ii][w + 8];
        float4 e0, e1;
        e0.x = (a.x + c0.x) * s0;  e0.y = (a.y + c0.y) * s0;
        e0.z = (a.z + c0.z) * s0;  e0.w = (a.w + c0.w) * s0;
        e1.x = (a.x + c1.x) * s1;  e1.y = (a.y + c1.y) * s1;
        e1.z = (a.z + c1.z) * s1;  e1.w = (a.w + c1.w) * s1;
        size_t rbase = base + (size_t)ii * (N_ * 32);
        __stcs(&e4[rbase + (size_t)w * 32],        e0);
        __stcs(&e4[rbase + (size_t)(w + 8) * 32],  e1);
        acc0.x += e0.x; acc0.y += e0.y; acc0.z += e0.z; acc0.w += e0.w;
        acc1.x += e1.x; acc1.y += e1.y; acc1.z += e1.z; acc1.w += e1.w;
    }

    // write partials: g_part[b][iy][j][f]  (FULL edge sums — nothing added later)
    float4* p4 = (float4*)g_part;
    size_t pbase = (((size_t)(b * NCH + iy) * N_) + j0) * 32 + lane;
    p4[pbase + (size_t)w * 32]       = acc0;
    p4[pbase + (size_t)(w + 8) * 32] = acc1;
}

// ---------------------------------------------------------------------------
// K3: fold partials (already complete edge sums), node_W GEMV + bias + h.
// 2 j-rows per block. grid = (N/2, B) = 1024 blocks, 128 threads (f).
// ---------------------------------------------------------------------------
__global__ __launch_bounds__(128) void k3_final(
    const float* __restrict__ nW, const float* __restrict__ nb,
    float* __restrict__ out1)
{
    const int b  = blockIdx.y;
    const int j0 = blockIdx.x * 2;
    const int f  = threadIdx.x;

    __shared__ float nn[2][FOUT];

    float acc0 = 0.f, acc1 = 0.f;
    #pragma unroll
    for (int c = 0; c < NCH; c++) {
        const float* pr = g_part + (((size_t)(b * NCH + c) * N_) + j0) * FOUT + f;
        acc0 += pr[0];
        acc1 += pr[FOUT];
    }
    nn[0][f] = acc0;
    nn[1][f] = acc1;
    __syncthreads();

    const float nbf = nb[f];
    float o0 = nbf, o1 = nbf;
    const float4* nwr = (const float4*)(nW + (size_t)f * FOUT);
    #pragma unroll 8
    for (int k = 0; k < 32; k++) {
        float4 w  = nwr[k];
        float4 n0 = ((const float4*)nn[0])[k];
        float4 n1 = ((const float4*)nn[1])[k];
        o0 += w.x*n0.x + w.y*n0.y + w.z*n0.z + w.w*n0.w;
        o1 += w.x*n1.x + w.y*n1.y + w.z*n1.z + w.w*n1.w;
    }

    const float* hr = g_h + ((size_t)(b * N_ + j0)) * FOUT;
    out1[((size_t)(b * N_ + j0))     * FOUT + f] = o0 + hr[f];
    out1[((size_t)(b * N_ + j0 + 1)) * FOUT + f] = o1 + hr[FOUT + f];
}

// ---------------------------------------------------------------------------
extern "C" void kernel_launch(void* const* d_in, const int* in_sizes, int n_in,
                              void* d_out, int out_size)
{
    const float* nodes = (const float*)d_in[0];
    const float* sk    = (const float*)d_in[1];
    const float* eW    = (const float*)d_in[2];
    const float* eb    = (const float*)d_in[3];
    const float* nW    = (const float*)d_in[4];
    const float* nb    = (const float*)d_in[5];
    const float* W0    = (const float*)d_in[6];
    const float* b0    = (const float*)d_in[7];
    const float* W1    = (const float*)d_in[8];
    const float* b1    = (const float*)d_in[9];
    const float* W2    = (const float*)d_in[10];
    const float* b2    = (const float*)d_in[11];

    float* out1  = (float*)d_out;                            // [B,N,F_OUT]
    float* edges = (float*)d_out + (size_t)B_ * N_ * FOUT;   // [B,N,N,F_OUT]

    k1_pernode<<<(B_ * N_) / 8, 256>>>(nodes, eW, eb, W0, b0, W1, b1, W2, b2);

    dim3 g2(N_ / 16, N_ / 64, B_);
    k2_edges<<<g2, 256>>>(sk, edges);

    dim3 g3(N_ / 2, B_);
    k3_final<<<g3, 128>>>(nW, nb, out1);
}